// round 4
// baseline (speedup 1.0000x reference)
#include <cuda_runtime.h>
#include <cstdint>

// ─────────────── helpers ───────────────
__device__ __forceinline__ uint32_t smem_u32(const void* p) {
    uint32_t a;
    asm("{ .reg .u64 t; cvta.to.shared.u64 t, %1; cvt.u32.u64 %0, t; }"
        : "=r"(a) : "l"(p));
    return a;
}
#define CP_ASYNC16(dst, src) \
    asm volatile("cp.async.cg.shared.global [%0], [%1], 16;" :: "r"(dst), "l"(src) : "memory")
#define CP_COMMIT()  asm volatile("cp.async.commit_group;" ::: "memory")
#define CP_WAIT0()   asm volatile("cp.async.wait_group 0;" ::: "memory")

// baseline tensor-core MMA (sm_80+): D(16x8) += A(16x8,row) * B(8x8,col), tf32
#define MMA_TF32(d, a, b) \
    asm volatile("mma.sync.aligned.m16n8k8.row.col.f32.tf32.tf32.f32 " \
        "{%0,%1,%2,%3}, {%4,%5,%6,%7}, {%8,%9}, {%0,%1,%2,%3};" \
        : "+f"((d)[0]), "+f"((d)[1]), "+f"((d)[2]), "+f"((d)[3]) \
        : "r"((a)[0]), "r"((a)[1]), "r"((a)[2]), "r"((a)[3]), "r"((b)[0]), "r"((b)[1]))

// ─────────────── globals ───────────────
static __device__ float g_c2[1024];
static __device__ int   g_maxcBits;
static __device__ float g_accum[2];            // [0]=sum m*||z-q||^2, [1]=sum m
static __device__ float g_candS[32768 * 16];   // per-token 16 approx candidates
static __device__ int   g_candI[32768 * 16];

__global__ void k_init() { g_accum[0] = 0.0f; g_accum[1] = 0.0f; g_maxcBits = 0; }

__global__ void k_c2(const float4* __restrict__ cb) {
    int k    = blockIdx.x * 8 + (threadIdx.x >> 5);
    int lane = threadIdx.x & 31;
    float4 a = cb[(size_t)k * 64 + lane];
    float4 b = cb[(size_t)k * 64 + 32 + lane];
    float s = a.x*a.x + a.y*a.y + a.z*a.z + a.w*a.w
            + b.x*b.x + b.y*b.y + b.z*b.z + b.w*b.w;
    #pragma unroll
    for (int o = 16; o; o >>= 1) s += __shfl_down_sync(0xffffffffu, s, o);
    if (lane == 0) {
        g_c2[k] = s;
        atomicMax(&g_maxcBits, __float_as_int(sqrtf(s)));
    }
}

// ─────────────── fused tf32 GEMM + in-register top-2 ───────────────
// CTA: 128 tokens x 1024 codes. 8 N-tiles of 128 codes, K=256 in 8 chunks of 32.
static constexpr int A_STRIDE = 36;                 // floats per row (pad)
static constexpr int A_CHUNK  = 128 * A_STRIDE * 4; // 18432 B
static constexpr int OFF_A0 = 0;
static constexpr int OFF_A1 = A_CHUNK;
static constexpr int OFF_B0 = 2 * A_CHUNK;
static constexpr int OFF_B1 = 3 * A_CHUNK;
static constexpr int DYN_SMEM = 4 * A_CHUNK;        // 73728 B -> 2 CTAs/SM

extern __shared__ char dynsmem[];

__device__ __forceinline__ void fill_chunk(uint32_t sbase, int it, int mtile,
                                           const float* __restrict__ z,
                                           const float* __restrict__ cb, int tid) {
    const int nt = it >> 3, kc = it & 7;
    const uint32_t bufA = sbase + ((it & 1) ? OFF_A1 : OFF_A0);
    const uint32_t bufB = sbase + ((it & 1) ? OFF_B1 : OFF_B0);
    const float* zsrc = z  + (size_t)mtile * 128 * 256 + kc * 32;
    const float* bsrc = cb + (size_t)nt    * 128 * 256 + kc * 32;
    #pragma unroll
    for (int i = 0; i < 4; i++) {
        int u = tid + i * 256, row = u >> 3, q = u & 7;
        CP_ASYNC16(bufA + row * (A_STRIDE * 4) + q * 16, zsrc + (size_t)row * 256 + q * 4);
        CP_ASYNC16(bufB + row * (A_STRIDE * 4) + q * 16, bsrc + (size_t)row * 256 + q * 4);
    }
}

__global__ void __launch_bounds__(256, 2) k_mma(const float* __restrict__ z,
                                                const float* __restrict__ cb) {
    __shared__ float c2sh[1024];

    const int tid  = threadIdx.x;
    const int wid  = tid >> 5;
    const int lane = tid & 31;
    const int g    = lane >> 2;     // groupID
    const int tg   = lane & 3;      // thread-in-group
    const int mw   = wid >> 1;      // m-warp 0..3  -> rows [mw*32, mw*32+32)
    const int nw   = wid & 1;       // n-warp 0..1  -> cols [nw*64, nw*64+64)
    const int mtile = blockIdx.x;

    uint32_t sbase = smem_u32(dynsmem);
    const float* As[2] = { (const float*)(dynsmem + OFF_A0), (const float*)(dynsmem + OFF_A1) };
    const float* Bs[2] = { (const float*)(dynsmem + OFF_B0), (const float*)(dynsmem + OFF_B1) };

    #pragma unroll
    for (int i = 0; i < 4; i++) c2sh[tid + i * 256] = g_c2[tid + i * 256];

    // per-thread top-2 for each of 4 owned rows (slot = mt*2 + half)
    float b1[4], b2[4]; int i1[4], i2[4];
    #pragma unroll
    for (int s = 0; s < 4; s++) { b1[s] = 3.0e38f; b2[s] = 3.0e38f; i1[s] = 0; i2[s] = 0; }

    float acc[2][8][4];

    fill_chunk(sbase, 0, mtile, z, cb, tid);
    CP_COMMIT();

    for (int it = 0; it < 64; it++) {
        const int p  = it & 1;
        const int kc = it & 7;
        const int nt = it >> 3;

        CP_WAIT0();
        __syncthreads();
        if (it + 1 < 64) { fill_chunk(sbase, it + 1, mtile, z, cb, tid); CP_COMMIT(); }

        if (kc == 0) {
            #pragma unroll
            for (int mt = 0; mt < 2; mt++)
                #pragma unroll
                for (int ntl = 0; ntl < 8; ntl++)
                    #pragma unroll
                    for (int r = 0; r < 4; r++) acc[mt][ntl][r] = 0.0f;
        }

        const uint32_t* A = (const uint32_t*)As[p];
        const uint32_t* B = (const uint32_t*)Bs[p];
        #pragma unroll
        for (int ks = 0; ks < 4; ks++) {
            const int ka = ks * 8;
            uint32_t af[2][4], bf[8][2];
            #pragma unroll
            for (int mt = 0; mt < 2; mt++) {
                int r0 = mw * 32 + mt * 16 + g;
                af[mt][0] = A[r0 * A_STRIDE + ka + tg];
                af[mt][1] = A[(r0 + 8) * A_STRIDE + ka + tg];
                af[mt][2] = A[r0 * A_STRIDE + ka + tg + 4];
                af[mt][3] = A[(r0 + 8) * A_STRIDE + ka + tg + 4];
            }
            #pragma unroll
            for (int ntl = 0; ntl < 8; ntl++) {
                int c0 = nw * 64 + ntl * 8 + g;
                bf[ntl][0] = B[c0 * A_STRIDE + ka + tg];
                bf[ntl][1] = B[c0 * A_STRIDE + ka + tg + 4];
            }
            #pragma unroll
            for (int mt = 0; mt < 2; mt++)
                #pragma unroll
                for (int ntl = 0; ntl < 8; ntl++)
                    MMA_TF32(acc[mt][ntl], af[mt], bf[ntl]);
        }

        if (kc == 7) {
            // fold this N-tile's scores into per-thread top-2 (registers only,
            // mma.sync results are ready; no barrier needed)
            #pragma unroll
            for (int mt = 0; mt < 2; mt++) {
                #pragma unroll
                for (int half = 0; half < 2; half++) {
                    const int slot = mt * 2 + half;
                    #pragma unroll
                    for (int ntl = 0; ntl < 8; ntl++) {
                        const int c0 = nt * 128 + nw * 64 + ntl * 8 + tg * 2;
                        #pragma unroll
                        for (int cc = 0; cc < 2; cc++) {
                            float s = fmaf(-2.0f, acc[mt][ntl][half * 2 + cc], c2sh[c0 + cc]);
                            if (s < b2[slot]) {
                                if (s < b1[slot]) {
                                    b2[slot] = b1[slot]; i2[slot] = i1[slot];
                                    b1[slot] = s;        i1[slot] = c0 + cc;
                                } else { b2[slot] = s; i2[slot] = c0 + cc; }
                            }
                        }
                    }
                }
            }
        }
    }

    // emit 16 candidates per token: 8 threads/row (2 nw x 4 tg) x top-2 each
    #pragma unroll
    for (int slot = 0; slot < 4; slot++) {
        const int row = mw * 32 + (slot >> 1) * 16 + g + (slot & 1) * 8;
        const size_t base = (size_t)(mtile * 128 + row) * 16 + (nw * 4 + tg) * 2;
        g_candS[base]     = b1[slot]; g_candI[base]     = i1[slot];
        g_candS[base + 1] = b2[slot]; g_candI[base + 1] = i2[slot];
    }
}

// ─────────── exact recheck + STE epilogue (1 warp / token) ───────────
__global__ void k_select(const float* __restrict__ z,
                         const float* __restrict__ mask,
                         const float* __restrict__ cb,
                         float* __restrict__ outQ,
                         float* __restrict__ outIdx) {
    __shared__ float zsh[8][256];
    __shared__ float sSum[8], sM[8];
    const int warp = threadIdx.x >> 5;
    const int lane = threadIdx.x & 31;
    const int token = blockIdx.x * 8 + warp;
    const float INF = __int_as_float(0x7f800000);

    float cs = INF; int ci = 0;
    if (lane < 16) {
        cs = g_candS[(size_t)token * 16 + lane];
        ci = g_candI[(size_t)token * 16 + lane];
    }
    // smin over all candidates; v = min over each thread's 2nd (odd slots)
    float smin = cs;
    #pragma unroll
    for (int o = 16; o; o >>= 1) smin = fminf(smin, __shfl_xor_sync(0xffffffffu, smin, o));
    float v = (lane < 16 && (lane & 1)) ? cs : INF;
    #pragma unroll
    for (int o = 16; o; o >>= 1) v = fminf(v, __shfl_xor_sync(0xffffffffu, v, o));

    const float4* z4 = (const float4*)(z + (size_t)token * 256) + lane * 2;
    float4 za = z4[0], zb = z4[1];
    float zn = za.x*za.x + za.y*za.y + za.z*za.z + za.w*za.w
             + zb.x*zb.x + zb.y*zb.y + zb.z*zb.z + zb.w*zb.w;
    #pragma unroll
    for (int o = 16; o; o >>= 1) zn += __shfl_xor_sync(0xffffffffu, zn, o);

    const float maxc = __int_as_float(g_maxcBits);
    // tf32 truncation: per-score error <= 2^-9 * ||z|| * maxc (conservative) + slack
    const float twoDelta = 2.0f * (2.2e-3f * sqrtf(zn) * maxc + 3e-2f);

    float bS; int bI;
    if (v > smin + twoDelta) {
        // true argmin provably among the 16 candidates -> exact fp32 recheck
        bS = INF; bI = 0x7fffffff;
        #pragma unroll 4
        for (int j = 0; j < 16; j++) {
            int idx = __shfl_sync(0xffffffffu, ci, j);
            const float4* c4 = (const float4*)(cb + (size_t)idx * 256) + lane * 2;
            float4 ca = c4[0], cc = c4[1];
            float d = za.x*ca.x + za.y*ca.y + za.z*ca.z + za.w*ca.w
                    + zb.x*cc.x + zb.y*cc.y + zb.z*cc.z + zb.w*cc.w;
            #pragma unroll
            for (int o = 16; o; o >>= 1) d += __shfl_xor_sync(0xffffffffu, d, o);
            float s = fmaf(-2.0f, d, g_c2[idx]);
            if (s < bS || (s == bS && idx < bI)) { bS = s; bI = idx; }
        }
    } else {
        // rare fallback: exact fp32 scan over all 1024 codes
        ((float4*)zsh[warp])[lane * 2] = za;
        ((float4*)zsh[warp])[lane * 2 + 1] = zb;
        __syncwarp();
        bS = INF; bI = 0x7fffffff;
        for (int c = lane; c < 1024; c += 32) {
            float d = 0.0f;
            for (int k = 0; k < 256; k++) d = fmaf(zsh[warp][k], cb[(size_t)c * 256 + k], d);
            float s = fmaf(-2.0f, d, g_c2[c]);
            if (s < bS || (s == bS && c < bI)) { bS = s; bI = c; }
        }
        #pragma unroll
        for (int o = 16; o; o >>= 1) {
            float s2 = __shfl_xor_sync(0xffffffffu, bS, o);
            int   i2 = __shfl_xor_sync(0xffffffffu, bI, o);
            if (s2 < bS || (s2 == bS && i2 < bI)) { bS = s2; bI = i2; }
        }
    }

    const int idx = bI;
    const float m = mask[token];
    const float4* q4 = (const float4*)(cb + (size_t)idx * 256) + lane * 2;
    float4 qa = q4[0], qb = q4[1];

    float ss = 0.0f;
    {
        float dx = za.x - qa.x, dy = za.y - qa.y, dz = za.z - qa.z, dw = za.w - qa.w;
        ss += dx*dx + dy*dy + dz*dz + dw*dw;
        dx = zb.x - qb.x; dy = zb.y - qb.y; dz = zb.z - qb.z; dw = zb.w - qb.w;
        ss += dx*dx + dy*dy + dz*dz + dw*dw;
    }
    float4* o4 = (float4*)(outQ + (size_t)token * 256) + lane * 2;
    float4 oa, ob;
    oa.x = (za.x + (qa.x - za.x)) * m; oa.y = (za.y + (qa.y - za.y)) * m;
    oa.z = (za.z + (qa.z - za.z)) * m; oa.w = (za.w + (qa.w - za.w)) * m;
    ob.x = (zb.x + (qb.x - zb.x)) * m; ob.y = (zb.y + (qb.y - zb.y)) * m;
    ob.z = (zb.z + (qb.z - zb.z)) * m; ob.w = (zb.w + (qb.w - zb.w)) * m;
    o4[0] = oa; o4[1] = ob;

    #pragma unroll
    for (int o = 16; o; o >>= 1) ss += __shfl_down_sync(0xffffffffu, ss, o);
    if (lane == 0) {
        sSum[warp] = ss * m;
        sM[warp]   = m;
        outIdx[token] = (m > 0.0f) ? (float)idx : 0.0f;
    }
    __syncthreads();
    if (threadIdx.x == 0) {
        float a = 0.0f, b = 0.0f;
        #pragma unroll
        for (int w = 0; w < 8; w++) { a += sSum[w]; b += sM[w]; }
        atomicAdd(&g_accum[0], a);
        atomicAdd(&g_accum[1], b);
    }
}

__global__ void k_finalize(float* outLoss) {
    outLoss[0] = 0.25f * (g_accum[0] / (g_accum[1] * 256.0f));
}

// ─────────────── launcher ───────────────
extern "C" void kernel_launch(void* const* d_in, const int* in_sizes, int n_in,
                              void* d_out, int out_size) {
    const float* z    = (const float*)d_in[0];   // (B,S,D)
    const float* mask = (const float*)d_in[1];   // (B,S)
    const float* cb   = (const float*)d_in[2];   // (K,D)

    const int BSD = in_sizes[0];                 // 8388608
    const int N   = in_sizes[1];                 // 32768

    float* out     = (float*)d_out;
    float* outQ    = out;
    float* outLoss = out + BSD;
    float* outIdx  = out + BSD + 1;

    cudaFuncSetAttribute(k_mma, cudaFuncAttributeMaxDynamicSharedMemorySize, DYN_SMEM);

    k_init<<<1, 1>>>();
    k_c2<<<128, 256>>>((const float4*)cb);
    k_mma<<<N / 128, 256, DYN_SMEM>>>(z, cb);
    k_select<<<N / 8, 256>>>(z, mask, cb, outQ, outIdx);
    k_finalize<<<1, 1>>>(outLoss);
}

// round 5
// speedup vs baseline: 3.0160x; 3.0160x over previous
#include <cuda_runtime.h>
#include <cstdint>

// ─────────────── helpers ───────────────
__device__ __forceinline__ uint32_t smem_u32(const void* p) {
    uint32_t a;
    asm("{ .reg .u64 t; cvta.to.shared.u64 t, %1; cvt.u32.u64 %0, t; }"
        : "=r"(a) : "l"(p));
    return a;
}
#define CP_ASYNC16(dst, src) \
    asm volatile("cp.async.cg.shared.global [%0], [%1], 16;" :: "r"(dst), "l"(src) : "memory")
#define CP_COMMIT()  asm volatile("cp.async.commit_group;" ::: "memory")
#define CP_WAIT0()   asm volatile("cp.async.wait_group 0;" ::: "memory")

// baseline tensor-core MMA (sm_80+): D(16x8) += A(16x8,row) * B(8x8,col), tf32
#define MMA_TF32(d, a, b) \
    asm volatile("mma.sync.aligned.m16n8k8.row.col.f32.tf32.tf32.f32 " \
        "{%0,%1,%2,%3}, {%4,%5,%6,%7}, {%8,%9}, {%0,%1,%2,%3};" \
        : "+f"((d)[0]), "+f"((d)[1]), "+f"((d)[2]), "+f"((d)[3]) \
        : "r"((a)[0]), "r"((a)[1]), "r"((a)[2]), "r"((a)[3]), "r"((b)[0]), "r"((b)[1]))

// ─────────────── globals ───────────────
static __device__ float g_c2[1024];
static __device__ int   g_maxcBits;
static __device__ float g_accum[2];            // [0]=sum m*||z-q||^2, [1]=sum m
static __device__ float g_candS[32768 * 16];   // per-token 16 approx candidates
static __device__ int   g_candI[32768 * 16];

__global__ void k_init() { g_accum[0] = 0.0f; g_accum[1] = 0.0f; g_maxcBits = 0; }

__global__ void k_c2(const float4* __restrict__ cb) {
    int k    = blockIdx.x * 8 + (threadIdx.x >> 5);
    int lane = threadIdx.x & 31;
    float4 a = cb[(size_t)k * 64 + lane];
    float4 b = cb[(size_t)k * 64 + 32 + lane];
    float s = a.x*a.x + a.y*a.y + a.z*a.z + a.w*a.w
            + b.x*b.x + b.y*b.y + b.z*b.z + b.w*b.w;
    #pragma unroll
    for (int o = 16; o; o >>= 1) s += __shfl_down_sync(0xffffffffu, s, o);
    if (lane == 0) {
        g_c2[k] = s;
        atomicMax(&g_maxcBits, __float_as_int(sqrtf(s)));
    }
}

// ─────────────── fused tf32 GEMM + in-register top-2 ───────────────
// CTA: 128 tokens x 1024 codes. 8 N-tiles of 128 codes, K=256 in 8 chunks of 32.
static constexpr int A_STRIDE = 36;                 // floats per row (pad)
static constexpr int A_CHUNK  = 128 * A_STRIDE * 4; // 18432 B
static constexpr int OFF_A0 = 0;
static constexpr int OFF_A1 = A_CHUNK;
static constexpr int OFF_B0 = 2 * A_CHUNK;
static constexpr int OFF_B1 = 3 * A_CHUNK;
static constexpr int DYN_SMEM = 4 * A_CHUNK;        // 73728 B -> 2 CTAs/SM

extern __shared__ char dynsmem[];

__device__ __forceinline__ void fill_chunk(uint32_t sbase, int it, int mtile,
                                           const float* __restrict__ z,
                                           const float* __restrict__ cb, int tid) {
    const int nt = it >> 3, kc = it & 7;
    const uint32_t bufA = sbase + ((it & 1) ? OFF_A1 : OFF_A0);
    const uint32_t bufB = sbase + ((it & 1) ? OFF_B1 : OFF_B0);
    const float* zsrc = z  + (size_t)mtile * 128 * 256 + kc * 32;
    const float* bsrc = cb + (size_t)nt    * 128 * 256 + kc * 32;
    #pragma unroll
    for (int i = 0; i < 4; i++) {
        int u = tid + i * 256, row = u >> 3, q = u & 7;
        CP_ASYNC16(bufA + row * (A_STRIDE * 4) + q * 16, zsrc + (size_t)row * 256 + q * 4);
        CP_ASYNC16(bufB + row * (A_STRIDE * 4) + q * 16, bsrc + (size_t)row * 256 + q * 4);
    }
}

__global__ void __launch_bounds__(256, 2) k_mma(const float* __restrict__ z,
                                                const float* __restrict__ cb) {
    __shared__ float c2sh[1024];

    const int tid  = threadIdx.x;
    const int wid  = tid >> 5;
    const int lane = tid & 31;
    const int g    = lane >> 2;     // groupID
    const int tg   = lane & 3;      // thread-in-group
    const int mw   = wid >> 1;      // m-warp 0..3  -> rows [mw*32, mw*32+32)
    const int nw   = wid & 1;       // n-warp 0..1  -> cols [nw*64, nw*64+64)
    const int mtile = blockIdx.x;

    uint32_t sbase = smem_u32(dynsmem);
    const float* As[2] = { (const float*)(dynsmem + OFF_A0), (const float*)(dynsmem + OFF_A1) };
    const float* Bs[2] = { (const float*)(dynsmem + OFF_B0), (const float*)(dynsmem + OFF_B1) };

    #pragma unroll
    for (int i = 0; i < 4; i++) c2sh[tid + i * 256] = g_c2[tid + i * 256];

    // per-thread top-2 for each of 4 owned rows (slot = mt*2 + half)
    float b1[4], b2[4]; int i1[4], i2[4];
    #pragma unroll
    for (int s = 0; s < 4; s++) { b1[s] = 3.0e38f; b2[s] = 3.0e38f; i1[s] = 0; i2[s] = 0; }

    float acc[2][8][4];

    fill_chunk(sbase, 0, mtile, z, cb, tid);
    CP_COMMIT();

    for (int it = 0; it < 64; it++) {
        const int p  = it & 1;
        const int kc = it & 7;
        const int nt = it >> 3;

        CP_WAIT0();
        __syncthreads();
        if (it + 1 < 64) { fill_chunk(sbase, it + 1, mtile, z, cb, tid); CP_COMMIT(); }

        if (kc == 0) {
            #pragma unroll
            for (int mt = 0; mt < 2; mt++)
                #pragma unroll
                for (int ntl = 0; ntl < 8; ntl++)
                    #pragma unroll
                    for (int r = 0; r < 4; r++) acc[mt][ntl][r] = 0.0f;
        }

        const uint32_t* A = (const uint32_t*)As[p];
        const uint32_t* B = (const uint32_t*)Bs[p];
        #pragma unroll
        for (int ks = 0; ks < 4; ks++) {
            const int ka = ks * 8;
            uint32_t af[2][4], bf[8][2];
            #pragma unroll
            for (int mt = 0; mt < 2; mt++) {
                int r0 = mw * 32 + mt * 16 + g;
                af[mt][0] = A[r0 * A_STRIDE + ka + tg];
                af[mt][1] = A[(r0 + 8) * A_STRIDE + ka + tg];
                af[mt][2] = A[r0 * A_STRIDE + ka + tg + 4];
                af[mt][3] = A[(r0 + 8) * A_STRIDE + ka + tg + 4];
            }
            #pragma unroll
            for (int ntl = 0; ntl < 8; ntl++) {
                int c0 = nw * 64 + ntl * 8 + g;
                bf[ntl][0] = B[c0 * A_STRIDE + ka + tg];
                bf[ntl][1] = B[c0 * A_STRIDE + ka + tg + 4];
            }
            #pragma unroll
            for (int mt = 0; mt < 2; mt++)
                #pragma unroll
                for (int ntl = 0; ntl < 8; ntl++)
                    MMA_TF32(acc[mt][ntl], af[mt], bf[ntl]);
        }

        if (kc == 7) {
            // fold this N-tile's scores into per-thread top-2 (registers only)
            #pragma unroll
            for (int mt = 0; mt < 2; mt++) {
                #pragma unroll
                for (int half = 0; half < 2; half++) {
                    const int slot = mt * 2 + half;
                    #pragma unroll
                    for (int ntl = 0; ntl < 8; ntl++) {
                        const int c0 = nt * 128 + nw * 64 + ntl * 8 + tg * 2;
                        #pragma unroll
                        for (int cc = 0; cc < 2; cc++) {
                            float s = fmaf(-2.0f, acc[mt][ntl][half * 2 + cc], c2sh[c0 + cc]);
                            if (s < b2[slot]) {
                                if (s < b1[slot]) {
                                    b2[slot] = b1[slot]; i2[slot] = i1[slot];
                                    b1[slot] = s;        i1[slot] = c0 + cc;
                                } else { b2[slot] = s; i2[slot] = c0 + cc; }
                            }
                        }
                    }
                }
            }
        }
    }

    // emit 16 candidates per token: 8 threads/row (2 nw x 4 tg) x top-2 each
    #pragma unroll
    for (int slot = 0; slot < 4; slot++) {
        const int row = mw * 32 + (slot >> 1) * 16 + (slot & 1) * 8 + g;
        const size_t base = (size_t)(mtile * 128 + row) * 16 + (nw * 4 + tg) * 2;
        g_candS[base]     = b1[slot]; g_candI[base]     = i1[slot];
        g_candS[base + 1] = b2[slot]; g_candI[base + 1] = i2[slot];
    }
}

// ─────────── exact recheck + STE epilogue (1 warp / token) ───────────
__global__ void k_select(const float* __restrict__ z,
                         const float* __restrict__ mask,
                         const float* __restrict__ cb,
                         float* __restrict__ outQ,
                         float* __restrict__ outIdx) {
    __shared__ float sSum[8], sM[8];
    const int warp = threadIdx.x >> 5;
    const int lane = threadIdx.x & 31;
    const int token = blockIdx.x * 8 + warp;
    const float INF = __int_as_float(0x7f800000);

    float cs = INF; int ci = 0;
    if (lane < 16) {
        cs = g_candS[(size_t)token * 16 + lane];
        ci = g_candI[(size_t)token * 16 + lane];
    }
    // v = min over each thread's 2nd-best (odd slots): every non-candidate
    // approx score is provably >= v
    float v = (lane < 16 && (lane & 1)) ? cs : INF;
    #pragma unroll
    for (int o = 16; o; o >>= 1) v = fminf(v, __shfl_xor_sync(0xffffffffu, v, o));

    const float4* z4 = (const float4*)(z + (size_t)token * 256) + lane * 2;
    const float4 za = z4[0], zb = z4[1];
    float zn = za.x*za.x + za.y*za.y + za.z*za.z + za.w*za.w
             + zb.x*zb.x + zb.y*zb.y + zb.z*zb.z + zb.w*zb.w;
    #pragma unroll
    for (int o = 16; o; o >>= 1) zn += __shfl_xor_sync(0xffffffffu, zn, o);

    const float maxc = __int_as_float(g_maxcBits);
    // tf32 truncation bound per score (conservative) + accumulation slack
    const float delta = 2.2e-3f * sqrtf(zn) * maxc + 3e-2f;

    // ALWAYS: exact fp32 recheck of the 16 candidates
    float bS = INF; int bI = 0x7fffffff;
    #pragma unroll 4
    for (int j = 0; j < 16; j++) {
        int idx = __shfl_sync(0xffffffffu, ci, j);
        const float4* c4 = (const float4*)(cb + (size_t)idx * 256) + lane * 2;
        float4 ca = c4[0], cc = c4[1];
        float d = za.x*ca.x + za.y*ca.y + za.z*ca.z + za.w*ca.w
                + zb.x*cc.x + zb.y*cc.y + zb.z*cc.z + zb.w*cc.w;
        #pragma unroll
        for (int o = 16; o; o >>= 1) d += __shfl_xor_sync(0xffffffffu, d, o);
        float s = fmaf(-2.0f, d, g_c2[idx]);
        if (s < bS || (s == bS && idx < bI)) { bS = s; bI = idx; }
    }

    // Certificate: non-candidates have exact score >= v - delta (strict win).
    if (!(bS < v - delta)) {
        // Cheap COALESCED full scan: warp cooperates per code, 8 codes in flight.
        for (int c0 = 0; c0 < 1024; c0 += 8) {
            float d[8];
            #pragma unroll
            for (int cc = 0; cc < 8; cc++) {
                const float4* c4 = (const float4*)(cb + (size_t)(c0 + cc) * 256) + lane * 2;
                float4 xa = c4[0], xb = c4[1];
                d[cc] = za.x*xa.x + za.y*xa.y + za.z*xa.z + za.w*xa.w
                      + zb.x*xb.x + zb.y*xb.y + zb.z*xb.z + zb.w*xb.w;
            }
            #pragma unroll
            for (int cc = 0; cc < 8; cc++) {
                #pragma unroll
                for (int o = 16; o; o >>= 1) d[cc] += __shfl_xor_sync(0xffffffffu, d[cc], o);
            }
            #pragma unroll
            for (int cc = 0; cc < 8; cc++) {
                float s = fmaf(-2.0f, d[cc], g_c2[c0 + cc]);
                int  cix = c0 + cc;
                if (s < bS || (s == bS && cix < bI)) { bS = s; bI = cix; }
            }
        }
    }

    const int idx = bI;
    const float m = mask[token];
    const float4* q4 = (const float4*)(cb + (size_t)idx * 256) + lane * 2;
    float4 qa = q4[0], qb = q4[1];

    float ss = 0.0f;
    {
        float dx = za.x - qa.x, dy = za.y - qa.y, dz = za.z - qa.z, dw = za.w - qa.w;
        ss += dx*dx + dy*dy + dz*dz + dw*dw;
        dx = zb.x - qb.x; dy = zb.y - qb.y; dz = zb.z - qb.z; dw = zb.w - qb.w;
        ss += dx*dx + dy*dy + dz*dz + dw*dw;
    }
    float4* o4 = (float4*)(outQ + (size_t)token * 256) + lane * 2;
    float4 oa, ob;
    oa.x = (za.x + (qa.x - za.x)) * m; oa.y = (za.y + (qa.y - za.y)) * m;
    oa.z = (za.z + (qa.z - za.z)) * m; oa.w = (za.w + (qa.w - za.w)) * m;
    ob.x = (zb.x + (qb.x - zb.x)) * m; ob.y = (zb.y + (qb.y - zb.y)) * m;
    ob.z = (zb.z + (qb.z - zb.z)) * m; ob.w = (zb.w + (qb.w - zb.w)) * m;
    o4[0] = oa; o4[1] = ob;

    #pragma unroll
    for (int o = 16; o; o >>= 1) ss += __shfl_down_sync(0xffffffffu, ss, o);
    if (lane == 0) {
        sSum[warp] = ss * m;
        sM[warp]   = m;
        outIdx[token] = (m > 0.0f) ? (float)idx : 0.0f;
    }
    __syncthreads();
    if (threadIdx.x == 0) {
        float a = 0.0f, b = 0.0f;
        #pragma unroll
        for (int w = 0; w < 8; w++) { a += sSum[w]; b += sM[w]; }
        atomicAdd(&g_accum[0], a);
        atomicAdd(&g_accum[1], b);
    }
}

__global__ void k_finalize(float* outLoss) {
    outLoss[0] = 0.25f * (g_accum[0] / (g_accum[1] * 256.0f));
}

// ─────────────── launcher ───────────────
extern "C" void kernel_launch(void* const* d_in, const int* in_sizes, int n_in,
                              void* d_out, int out_size) {
    const float* z    = (const float*)d_in[0];   // (B,S,D)
    const float* mask = (const float*)d_in[1];   // (B,S)
    const float* cb   = (const float*)d_in[2];   // (K,D)

    const int BSD = in_sizes[0];                 // 8388608
    const int N   = in_sizes[1];                 // 32768

    float* out     = (float*)d_out;
    float* outQ    = out;
    float* outLoss = out + BSD;
    float* outIdx  = out + BSD + 1;

    cudaFuncSetAttribute(k_mma, cudaFuncAttributeMaxDynamicSharedMemorySize, DYN_SMEM);

    k_init<<<1, 1>>>();
    k_c2<<<128, 256>>>((const float4*)cb);
    k_mma<<<N / 128, 256, DYN_SMEM>>>(z, cb);
    k_select<<<N / 8, 256>>>(z, mask, cb, outQ, outIdx);
    k_finalize<<<1, 1>>>(outLoss);
}

// round 6
// speedup vs baseline: 3.0924x; 1.0253x over previous
#include <cuda_runtime.h>
#include <cstdint>

// ─────────────── helpers ───────────────
__device__ __forceinline__ uint32_t smem_u32(const void* p) {
    uint32_t a;
    asm("{ .reg .u64 t; cvta.to.shared.u64 t, %1; cvt.u32.u64 %0, t; }"
        : "=r"(a) : "l"(p));
    return a;
}
#define CP_ASYNC16(dst, src) \
    asm volatile("cp.async.cg.shared.global [%0], [%1], 16;" :: "r"(dst), "l"(src) : "memory")
#define CP_COMMIT()  asm volatile("cp.async.commit_group;" ::: "memory")
#define CP_WAIT0()   asm volatile("cp.async.wait_group 0;" ::: "memory")

// baseline tensor-core MMA (sm_80+): D(16x8) += A(16x8,row) * B(8x8,col), tf32
#define MMA_TF32(d, a, b) \
    asm volatile("mma.sync.aligned.m16n8k8.row.col.f32.tf32.tf32.f32 " \
        "{%0,%1,%2,%3}, {%4,%5,%6,%7}, {%8,%9}, {%0,%1,%2,%3};" \
        : "+f"((d)[0]), "+f"((d)[1]), "+f"((d)[2]), "+f"((d)[3]) \
        : "r"((a)[0]), "r"((a)[1]), "r"((a)[2]), "r"((a)[3]), "r"((b)[0]), "r"((b)[1]))

// ─────────────── globals ───────────────
static __device__ float g_c2[1024];
static __device__ int   g_maxcBits;
static __device__ float g_accum[2];            // [0]=sum m*||z-q||^2, [1]=sum m
static __device__ float g_candS[32768 * 24];   // per-token 24 approx candidates
static __device__ int   g_candI[32768 * 24];

__global__ void k_init() { g_accum[0] = 0.0f; g_accum[1] = 0.0f; g_maxcBits = 0; }

__global__ void k_c2(const float4* __restrict__ cb) {
    int k    = blockIdx.x * 8 + (threadIdx.x >> 5);
    int lane = threadIdx.x & 31;
    float4 a = cb[(size_t)k * 64 + lane];
    float4 b = cb[(size_t)k * 64 + 32 + lane];
    float s = a.x*a.x + a.y*a.y + a.z*a.z + a.w*a.w
            + b.x*b.x + b.y*b.y + b.z*b.z + b.w*b.w;
    #pragma unroll
    for (int o = 16; o; o >>= 1) s += __shfl_down_sync(0xffffffffu, s, o);
    if (lane == 0) {
        g_c2[k] = s;
        atomicMax(&g_maxcBits, __float_as_int(sqrtf(s)));
    }
}

// ─────────────── fused tf32 GEMM + in-register top-3 ───────────────
// CTA: 128 tokens x 1024 codes. 8 N-tiles of 128 codes, K=256 in 8 chunks of 32.
static constexpr int A_STRIDE = 36;                 // floats per row (pad)
static constexpr int A_CHUNK  = 128 * A_STRIDE * 4; // 18432 B
static constexpr int OFF_A0 = 0;
static constexpr int OFF_A1 = A_CHUNK;
static constexpr int OFF_B0 = 2 * A_CHUNK;
static constexpr int OFF_B1 = 3 * A_CHUNK;
static constexpr int DYN_SMEM = 4 * A_CHUNK;        // 73728 B -> 2 CTAs/SM

extern __shared__ char dynsmem[];

__device__ __forceinline__ void fill_chunk(uint32_t sbase, int it, int mtile,
                                           const float* __restrict__ z,
                                           const float* __restrict__ cb, int tid) {
    const int nt = it >> 3, kc = it & 7;
    const uint32_t bufA = sbase + ((it & 1) ? OFF_A1 : OFF_A0);
    const uint32_t bufB = sbase + ((it & 1) ? OFF_B1 : OFF_B0);
    const float* zsrc = z  + (size_t)mtile * 128 * 256 + kc * 32;
    const float* bsrc = cb + (size_t)nt    * 128 * 256 + kc * 32;
    #pragma unroll
    for (int i = 0; i < 4; i++) {
        int u = tid + i * 256, row = u >> 3, q = u & 7;
        CP_ASYNC16(bufA + row * (A_STRIDE * 4) + q * 16, zsrc + (size_t)row * 256 + q * 4);
        CP_ASYNC16(bufB + row * (A_STRIDE * 4) + q * 16, bsrc + (size_t)row * 256 + q * 4);
    }
}

__global__ void __launch_bounds__(256, 2) k_mma(const float* __restrict__ z,
                                                const float* __restrict__ cb) {
    __shared__ float c2sh[1024];

    const int tid  = threadIdx.x;
    const int wid  = tid >> 5;
    const int lane = tid & 31;
    const int g    = lane >> 2;     // groupID
    const int tg   = lane & 3;      // thread-in-group
    const int mw   = wid >> 1;      // m-warp 0..3  -> rows [mw*32, mw*32+32)
    const int nw   = wid & 1;       // n-warp 0..1  -> cols [nw*64, nw*64+64)
    const int mtile = blockIdx.x;

    uint32_t sbase = smem_u32(dynsmem);
    const float* As[2] = { (const float*)(dynsmem + OFF_A0), (const float*)(dynsmem + OFF_A1) };
    const float* Bs[2] = { (const float*)(dynsmem + OFF_B0), (const float*)(dynsmem + OFF_B1) };

    #pragma unroll
    for (int i = 0; i < 4; i++) c2sh[tid + i * 256] = g_c2[tid + i * 256];

    // per-thread top-3 for each of 4 owned rows (slot = mt*2 + half)
    float b1[4], b2[4], b3[4]; int i1[4], i2[4], i3[4];
    #pragma unroll
    for (int s = 0; s < 4; s++) {
        b1[s] = 3.0e38f; b2[s] = 3.0e38f; b3[s] = 3.0e38f;
        i1[s] = 0; i2[s] = 0; i3[s] = 0;
    }

    float acc[2][8][4];

    fill_chunk(sbase, 0, mtile, z, cb, tid);
    CP_COMMIT();

    for (int it = 0; it < 64; it++) {
        const int p  = it & 1;
        const int kc = it & 7;
        const int nt = it >> 3;

        CP_WAIT0();
        __syncthreads();
        if (it + 1 < 64) { fill_chunk(sbase, it + 1, mtile, z, cb, tid); CP_COMMIT(); }

        if (kc == 0) {
            #pragma unroll
            for (int mt = 0; mt < 2; mt++)
                #pragma unroll
                for (int ntl = 0; ntl < 8; ntl++)
                    #pragma unroll
                    for (int r = 0; r < 4; r++) acc[mt][ntl][r] = 0.0f;
        }

        const uint32_t* A = (const uint32_t*)As[p];
        const uint32_t* B = (const uint32_t*)Bs[p];
        #pragma unroll
        for (int ks = 0; ks < 4; ks++) {
            const int ka = ks * 8;
            uint32_t af[2][4], bf[8][2];
            #pragma unroll
            for (int mt = 0; mt < 2; mt++) {
                int r0 = mw * 32 + mt * 16 + g;
                af[mt][0] = A[r0 * A_STRIDE + ka + tg];
                af[mt][1] = A[(r0 + 8) * A_STRIDE + ka + tg];
                af[mt][2] = A[r0 * A_STRIDE + ka + tg + 4];
                af[mt][3] = A[(r0 + 8) * A_STRIDE + ka + tg + 4];
            }
            #pragma unroll
            for (int ntl = 0; ntl < 8; ntl++) {
                int c0 = nw * 64 + ntl * 8 + g;
                bf[ntl][0] = B[c0 * A_STRIDE + ka + tg];
                bf[ntl][1] = B[c0 * A_STRIDE + ka + tg + 4];
            }
            #pragma unroll
            for (int mt = 0; mt < 2; mt++)
                #pragma unroll
                for (int ntl = 0; ntl < 8; ntl++)
                    MMA_TF32(acc[mt][ntl], af[mt], bf[ntl]);
        }

        if (kc == 7) {
            // fold this N-tile's scores into per-thread top-3 (registers only)
            #pragma unroll
            for (int mt = 0; mt < 2; mt++) {
                #pragma unroll
                for (int half = 0; half < 2; half++) {
                    const int slot = mt * 2 + half;
                    #pragma unroll
                    for (int ntl = 0; ntl < 8; ntl++) {
                        const int c0 = nt * 128 + nw * 64 + ntl * 8 + tg * 2;
                        #pragma unroll
                        for (int cc = 0; cc < 2; cc++) {
                            float s = fmaf(-2.0f, acc[mt][ntl][half * 2 + cc], c2sh[c0 + cc]);
                            if (s < b3[slot]) {
                                if (s < b2[slot]) {
                                    b3[slot] = b2[slot]; i3[slot] = i2[slot];
                                    if (s < b1[slot]) {
                                        b2[slot] = b1[slot]; i2[slot] = i1[slot];
                                        b1[slot] = s;        i1[slot] = c0 + cc;
                                    } else { b2[slot] = s; i2[slot] = c0 + cc; }
                                } else { b3[slot] = s; i3[slot] = c0 + cc; }
                            }
                        }
                    }
                }
            }
        }
    }

    // emit 24 candidates per token: 8 threads/row (2 nw x 4 tg) x top-3 each
    #pragma unroll
    for (int slot = 0; slot < 4; slot++) {
        const int row = mw * 32 + (slot >> 1) * 16 + (slot & 1) * 8 + g;
        const size_t base = (size_t)(mtile * 128 + row) * 24 + (nw * 4 + tg) * 3;
        g_candS[base]     = b1[slot]; g_candI[base]     = i1[slot];
        g_candS[base + 1] = b2[slot]; g_candI[base + 1] = i2[slot];
        g_candS[base + 2] = b3[slot]; g_candI[base + 2] = i3[slot];
    }
}

// ─────────── exact recheck + STE epilogue (1 warp / token) ───────────
__global__ void k_select(const float* __restrict__ z,
                         const float* __restrict__ mask,
                         const float* __restrict__ cb,
                         float* __restrict__ outQ,
                         float* __restrict__ outIdx) {
    __shared__ float sSum[8], sM[8];
    const int warp = threadIdx.x >> 5;
    const int lane = threadIdx.x & 31;
    const int token = blockIdx.x * 8 + warp;
    const float INF = __int_as_float(0x7f800000);

    float cs = INF; int ci = 0;
    if (lane < 24) {
        cs = g_candS[(size_t)token * 24 + lane];
        ci = g_candI[(size_t)token * 24 + lane];
    }
    // v = min over each thread's 3rd-best (lane%3==2): every non-candidate
    // approx score is provably >= v
    float v = (lane < 24 && (lane % 3) == 2) ? cs : INF;
    #pragma unroll
    for (int o = 16; o; o >>= 1) v = fminf(v, __shfl_xor_sync(0xffffffffu, v, o));

    const float4* z4 = (const float4*)(z + (size_t)token * 256) + lane * 2;
    const float4 za = z4[0], zb = z4[1];
    float zn = za.x*za.x + za.y*za.y + za.z*za.z + za.w*za.w
             + zb.x*zb.x + zb.y*zb.y + zb.z*zb.z + zb.w*zb.w;
    #pragma unroll
    for (int o = 16; o; o >>= 1) zn += __shfl_xor_sync(0xffffffffu, zn, o);

    const float maxc = __int_as_float(g_maxcBits);
    // tf32 truncation bound per score (conservative) + accumulation slack
    const float delta = 2.2e-3f * sqrtf(zn) * maxc + 3e-2f;

    // ALWAYS: exact fp32 recheck of the 24 candidates
    float bS = INF; int bI = 0x7fffffff;
    #pragma unroll 4
    for (int j = 0; j < 24; j++) {
        int idx = __shfl_sync(0xffffffffu, ci, j);
        const float4* c4 = (const float4*)(cb + (size_t)idx * 256) + lane * 2;
        float4 ca = c4[0], cc = c4[1];
        float d = za.x*ca.x + za.y*ca.y + za.z*ca.z + za.w*ca.w
                + zb.x*cc.x + zb.y*cc.y + zb.z*cc.z + zb.w*cc.w;
        #pragma unroll
        for (int o = 16; o; o >>= 1) d += __shfl_xor_sync(0xffffffffu, d, o);
        float s = fmaf(-2.0f, d, g_c2[idx]);
        if (s < bS || (s == bS && idx < bI)) { bS = s; bI = idx; }
    }

    // Certificate: non-candidates have exact score >= v - delta (strict win).
    if (!(bS < v - delta)) {
        // Rare COALESCED full scan: warp cooperates per code, 8 codes in flight.
        for (int c0 = 0; c0 < 1024; c0 += 8) {
            float d[8];
            #pragma unroll
            for (int cc = 0; cc < 8; cc++) {
                const float4* c4 = (const float4*)(cb + (size_t)(c0 + cc) * 256) + lane * 2;
                float4 xa = c4[0], xb = c4[1];
                d[cc] = za.x*xa.x + za.y*xa.y + za.z*xa.z + za.w*xa.w
                      + zb.x*xb.x + zb.y*xb.y + zb.z*xb.z + zb.w*xb.w;
            }
            #pragma unroll
            for (int cc = 0; cc < 8; cc++) {
                #pragma unroll
                for (int o = 16; o; o >>= 1) d[cc] += __shfl_xor_sync(0xffffffffu, d[cc], o);
            }
            #pragma unroll
            for (int cc = 0; cc < 8; cc++) {
                float s = fmaf(-2.0f, d[cc], g_c2[c0 + cc]);
                int  cix = c0 + cc;
                if (s < bS || (s == bS && cix < bI)) { bS = s; bI = cix; }
            }
        }
    }

    const int idx = bI;
    const float m = mask[token];
    const float4* q4 = (const float4*)(cb + (size_t)idx * 256) + lane * 2;
    float4 qa = q4[0], qb = q4[1];

    float ss = 0.0f;
    {
        float dx = za.x - qa.x, dy = za.y - qa.y, dz = za.z - qa.z, dw = za.w - qa.w;
        ss += dx*dx + dy*dy + dz*dz + dw*dw;
        dx = zb.x - qb.x; dy = zb.y - qb.y; dz = zb.z - qb.z; dw = zb.w - qb.w;
        ss += dx*dx + dy*dy + dz*dz + dw*dw;
    }
    float4* o4 = (float4*)(outQ + (size_t)token * 256) + lane * 2;
    float4 oa, ob;
    oa.x = (za.x + (qa.x - za.x)) * m; oa.y = (za.y + (qa.y - za.y)) * m;
    oa.z = (za.z + (qa.z - za.z)) * m; oa.w = (za.w + (qa.w - za.w)) * m;
    ob.x = (zb.x + (qb.x - zb.x)) * m; ob.y = (zb.y + (qb.y - zb.y)) * m;
    ob.z = (zb.z + (qb.z - zb.z)) * m; ob.w = (zb.w + (qb.w - zb.w)) * m;
    o4[0] = oa; o4[1] = ob;

    #pragma unroll
    for (int o = 16; o; o >>= 1) ss += __shfl_down_sync(0xffffffffu, ss, o);
    if (lane == 0) {
        sSum[warp] = ss * m;
        sM[warp]   = m;
        outIdx[token] = (m > 0.0f) ? (float)idx : 0.0f;
    }
    __syncthreads();
    if (threadIdx.x == 0) {
        float a = 0.0f, b = 0.0f;
        #pragma unroll
        for (int w = 0; w < 8; w++) { a += sSum[w]; b += sM[w]; }
        atomicAdd(&g_accum[0], a);
        atomicAdd(&g_accum[1], b);
    }
}

__global__ void k_finalize(float* outLoss) {
    outLoss[0] = 0.25f * (g_accum[0] / (g_accum[1] * 256.0f));
}

// ─────────────── launcher ───────────────
extern "C" void kernel_launch(void* const* d_in, const int* in_sizes, int n_in,
                              void* d_out, int out_size) {
    const float* z    = (const float*)d_in[0];   // (B,S,D)
    const float* mask = (const float*)d_in[1];   // (B,S)
    const float* cb   = (const float*)d_in[2];   // (K,D)

    const int BSD = in_sizes[0];                 // 8388608
    const int N   = in_sizes[1];                 // 32768

    float* out     = (float*)d_out;
    float* outQ    = out;
    float* outLoss = out + BSD;
    float* outIdx  = out + BSD + 1;

    cudaFuncSetAttribute(k_mma, cudaFuncAttributeMaxDynamicSharedMemorySize, DYN_SMEM);

    k_init<<<1, 1>>>();
    k_c2<<<128, 256>>>((const float4*)cb);
    k_mma<<<N / 128, 256, DYN_SMEM>>>(z, cb);
    k_select<<<N / 8, 256>>>(z, mask, cb, outQ, outIdx);
    k_finalize<<<1, 1>>>(outLoss);
}

// round 7
// speedup vs baseline: 3.3900x; 1.0962x over previous
#include <cuda_runtime.h>
#include <cstdint>

// ─────────────── helpers ───────────────
__device__ __forceinline__ uint32_t smem_u32(const void* p) {
    uint32_t a;
    asm("{ .reg .u64 t; cvta.to.shared.u64 t, %1; cvt.u32.u64 %0, t; }"
        : "=r"(a) : "l"(p));
    return a;
}
#define CP_ASYNC16(dst, src) \
    asm volatile("cp.async.cg.shared.global [%0], [%1], 16;" :: "r"(dst), "l"(src) : "memory")
#define CP_COMMIT()  asm volatile("cp.async.commit_group;" ::: "memory")
#define CP_WAIT0()   asm volatile("cp.async.wait_group 0;" ::: "memory")

// baseline tensor-core MMA (sm_80+): D(16x8) += A(16x8,row) * B(8x8,col), tf32
#define MMA_TF32(d, a, b) \
    asm volatile("mma.sync.aligned.m16n8k8.row.col.f32.tf32.tf32.f32 " \
        "{%0,%1,%2,%3}, {%4,%5,%6,%7}, {%8,%9}, {%0,%1,%2,%3};" \
        : "+f"((d)[0]), "+f"((d)[1]), "+f"((d)[2]), "+f"((d)[3]) \
        : "r"((a)[0]), "r"((a)[1]), "r"((a)[2]), "r"((a)[3]), "r"((b)[0]), "r"((b)[1]))

// ─────────────── globals ───────────────
static __device__ float g_c2[1024];
static __device__ int   g_maxcBits;
static __device__ float g_accum[2];            // [0]=sum m*||z-q||^2, [1]=sum m
static __device__ float g_candS[32768 * 24];   // per-token 24 approx candidates
static __device__ int   g_candI[32768 * 24];

__global__ void k_init() { g_accum[0] = 0.0f; g_accum[1] = 0.0f; g_maxcBits = 0; }

__global__ void k_c2(const float4* __restrict__ cb) {
    int k    = blockIdx.x * 8 + (threadIdx.x >> 5);
    int lane = threadIdx.x & 31;
    float4 a = cb[(size_t)k * 64 + lane];
    float4 b = cb[(size_t)k * 64 + 32 + lane];
    float s = a.x*a.x + a.y*a.y + a.z*a.z + a.w*a.w
            + b.x*b.x + b.y*b.y + b.z*b.z + b.w*b.w;
    #pragma unroll
    for (int o = 16; o; o >>= 1) s += __shfl_down_sync(0xffffffffu, s, o);
    if (lane == 0) {
        g_c2[k] = s;
        atomicMax(&g_maxcBits, __float_as_int(sqrtf(s)));
    }
}

// ─────────────── fused tf32 GEMM + in-register top-3 ───────────────
// CTA: 128 tokens x 1024 codes. 8 N-tiles of 128 codes, K=256 in 8 chunks of 32.
static constexpr int A_STRIDE = 36;                 // floats per row (pad)
static constexpr int A_CHUNK  = 128 * A_STRIDE * 4; // 18432 B
static constexpr int OFF_A0 = 0;
static constexpr int OFF_A1 = A_CHUNK;
static constexpr int OFF_B0 = 2 * A_CHUNK;
static constexpr int OFF_B1 = 3 * A_CHUNK;
static constexpr int DYN_SMEM = 4 * A_CHUNK;        // 73728 B -> 2 CTAs/SM

extern __shared__ char dynsmem[];

__device__ __forceinline__ void fill_chunk(uint32_t sbase, int it, int mtile,
                                           const float* __restrict__ z,
                                           const float* __restrict__ cb, int tid) {
    const int nt = it >> 3, kc = it & 7;
    const uint32_t bufA = sbase + ((it & 1) ? OFF_A1 : OFF_A0);
    const uint32_t bufB = sbase + ((it & 1) ? OFF_B1 : OFF_B0);
    const float* zsrc = z  + (size_t)mtile * 128 * 256 + kc * 32;
    const float* bsrc = cb + (size_t)nt    * 128 * 256 + kc * 32;
    #pragma unroll
    for (int i = 0; i < 4; i++) {
        int u = tid + i * 256, row = u >> 3, q = u & 7;
        CP_ASYNC16(bufA + row * (A_STRIDE * 4) + q * 16, zsrc + (size_t)row * 256 + q * 4);
        CP_ASYNC16(bufB + row * (A_STRIDE * 4) + q * 16, bsrc + (size_t)row * 256 + q * 4);
    }
}

__global__ void __launch_bounds__(256, 2) k_mma(const float* __restrict__ z,
                                                const float* __restrict__ cb) {
    __shared__ float c2sh[1024];

    const int tid  = threadIdx.x;
    const int wid  = tid >> 5;
    const int lane = tid & 31;
    const int g    = lane >> 2;     // groupID
    const int tg   = lane & 3;      // thread-in-group
    const int mw   = wid >> 1;      // m-warp 0..3  -> rows [mw*32, mw*32+32)
    const int nw   = wid & 1;       // n-warp 0..1  -> cols [nw*64, nw*64+64)
    const int mtile = blockIdx.x;

    uint32_t sbase = smem_u32(dynsmem);
    const float* As[2] = { (const float*)(dynsmem + OFF_A0), (const float*)(dynsmem + OFF_A1) };
    const float* Bs[2] = { (const float*)(dynsmem + OFF_B0), (const float*)(dynsmem + OFF_B1) };

    #pragma unroll
    for (int i = 0; i < 4; i++) c2sh[tid + i * 256] = g_c2[tid + i * 256];

    // per-thread top-3 for each of 4 owned rows (slot = mt*2 + half)
    float b1[4], b2[4], b3[4]; int i1[4], i2[4], i3[4];
    #pragma unroll
    for (int s = 0; s < 4; s++) {
        b1[s] = 3.0e38f; b2[s] = 3.0e38f; b3[s] = 3.0e38f;
        i1[s] = 0; i2[s] = 0; i3[s] = 0;
    }

    float acc[2][8][4];

    fill_chunk(sbase, 0, mtile, z, cb, tid);
    CP_COMMIT();

    for (int it = 0; it < 64; it++) {
        const int p  = it & 1;
        const int kc = it & 7;
        const int nt = it >> 3;

        CP_WAIT0();
        __syncthreads();
        if (it + 1 < 64) { fill_chunk(sbase, it + 1, mtile, z, cb, tid); CP_COMMIT(); }

        if (kc == 0) {
            #pragma unroll
            for (int mt = 0; mt < 2; mt++)
                #pragma unroll
                for (int ntl = 0; ntl < 8; ntl++)
                    #pragma unroll
                    for (int r = 0; r < 4; r++) acc[mt][ntl][r] = 0.0f;
        }

        const uint32_t* A = (const uint32_t*)As[p];
        const uint32_t* B = (const uint32_t*)Bs[p];
        #pragma unroll
        for (int ks = 0; ks < 4; ks++) {
            const int ka = ks * 8;
            uint32_t af[2][4], bf[8][2];
            #pragma unroll
            for (int mt = 0; mt < 2; mt++) {
                int r0 = mw * 32 + mt * 16 + g;
                af[mt][0] = A[r0 * A_STRIDE + ka + tg];
                af[mt][1] = A[(r0 + 8) * A_STRIDE + ka + tg];
                af[mt][2] = A[r0 * A_STRIDE + ka + tg + 4];
                af[mt][3] = A[(r0 + 8) * A_STRIDE + ka + tg + 4];
            }
            #pragma unroll
            for (int ntl = 0; ntl < 8; ntl++) {
                int c0 = nw * 64 + ntl * 8 + g;
                bf[ntl][0] = B[c0 * A_STRIDE + ka + tg];
                bf[ntl][1] = B[c0 * A_STRIDE + ka + tg + 4];
            }
            #pragma unroll
            for (int mt = 0; mt < 2; mt++)
                #pragma unroll
                for (int ntl = 0; ntl < 8; ntl++)
                    MMA_TF32(acc[mt][ntl], af[mt], bf[ntl]);
        }

        if (kc == 7) {
            // fold this N-tile's scores into per-thread top-3 (registers only)
            #pragma unroll
            for (int mt = 0; mt < 2; mt++) {
                #pragma unroll
                for (int half = 0; half < 2; half++) {
                    const int slot = mt * 2 + half;
                    #pragma unroll
                    for (int ntl = 0; ntl < 8; ntl++) {
                        const int c0 = nt * 128 + nw * 64 + ntl * 8 + tg * 2;
                        #pragma unroll
                        for (int cc = 0; cc < 2; cc++) {
                            float s = fmaf(-2.0f, acc[mt][ntl][half * 2 + cc], c2sh[c0 + cc]);
                            if (s < b3[slot]) {
                                if (s < b2[slot]) {
                                    b3[slot] = b2[slot]; i3[slot] = i2[slot];
                                    if (s < b1[slot]) {
                                        b2[slot] = b1[slot]; i2[slot] = i1[slot];
                                        b1[slot] = s;        i1[slot] = c0 + cc;
                                    } else { b2[slot] = s; i2[slot] = c0 + cc; }
                                } else { b3[slot] = s; i3[slot] = c0 + cc; }
                            }
                        }
                    }
                }
            }
        }
    }

    // emit 24 candidates per token: 8 threads/row (2 nw x 4 tg) x top-3 each
    #pragma unroll
    for (int slot = 0; slot < 4; slot++) {
        const int row = mw * 32 + (slot >> 1) * 16 + (slot & 1) * 8 + g;
        const size_t base = (size_t)(mtile * 128 + row) * 24 + (nw * 4 + tg) * 3;
        g_candS[base]     = b1[slot]; g_candI[base]     = i1[slot];
        g_candS[base + 1] = b2[slot]; g_candI[base + 1] = i2[slot];
        g_candS[base + 2] = b3[slot]; g_candI[base + 2] = i3[slot];
    }
}

// ─────────── certified select + STE epilogue (1 warp / token) ───────────
__global__ void k_select(const float* __restrict__ z,
                         const float* __restrict__ mask,
                         const float* __restrict__ cb,
                         float* __restrict__ outQ,
                         float* __restrict__ outIdx) {
    __shared__ float sSum[8], sM[8];
    const int warp = threadIdx.x >> 5;
    const int lane = threadIdx.x & 31;
    const int token = blockIdx.x * 8 + warp;
    const float INF = __int_as_float(0x7f800000);

    float cs = INF; int ci = 0x7fffffff;
    if (lane < 24) {
        cs = g_candS[(size_t)token * 24 + lane];
        ci = g_candI[(size_t)token * 24 + lane];
    }

    // global approx argmin (candidates provably contain global top-2; indices distinct)
    float s1 = cs; int idx1 = ci;
    #pragma unroll
    for (int o = 16; o; o >>= 1) {
        float so = __shfl_xor_sync(0xffffffffu, s1, o);
        int   io = __shfl_xor_sync(0xffffffffu, idx1, o);
        if (so < s1 || (so == s1 && io < idx1)) { s1 = so; idx1 = io; }
    }
    // global approx 2nd-best = min over candidates excluding the argmin one
    float sx = (ci == idx1) ? INF : cs;
    #pragma unroll
    for (int o = 16; o; o >>= 1) sx = fminf(sx, __shfl_xor_sync(0xffffffffu, sx, o));
    // v = min over each thread's 3rd-best: non-candidates are provably >= v
    float v = (lane < 24 && (lane % 3) == 2) ? cs : INF;
    #pragma unroll
    for (int o = 16; o; o >>= 1) v = fminf(v, __shfl_xor_sync(0xffffffffu, v, o));

    const float4* z4 = (const float4*)(z + (size_t)token * 256) + lane * 2;
    const float4 za = z4[0], zb = z4[1];
    float zn = za.x*za.x + za.y*za.y + za.z*za.z + za.w*za.w
             + zb.x*zb.x + zb.y*zb.y + zb.z*zb.z + zb.w*zb.w;
    #pragma unroll
    for (int o = 16; o; o >>= 1) zn += __shfl_xor_sync(0xffffffffu, zn, o);

    const float maxc = __int_as_float(g_maxcBits);
    // sound tf32 truncation bound per score + accumulation slack
    const float delta = 2.2e-3f * sqrtf(zn) * maxc + 3e-2f;

    int bI;
    if (sx - s1 > 2.0f * delta) {
        // approx argmin == exact argmin, certified; no recheck needed
        bI = idx1;
    } else {
        // exact fp32 recheck of the 24 candidates
        float bS = INF; bI = 0x7fffffff;
        #pragma unroll 4
        for (int j = 0; j < 24; j++) {
            int idx = __shfl_sync(0xffffffffu, ci, j);
            const float4* c4 = (const float4*)(cb + (size_t)idx * 256) + lane * 2;
            float4 ca = c4[0], cc = c4[1];
            float d = za.x*ca.x + za.y*ca.y + za.z*ca.z + za.w*ca.w
                    + zb.x*cc.x + zb.y*cc.y + zb.z*cc.z + zb.w*cc.w;
            #pragma unroll
            for (int o = 16; o; o >>= 1) d += __shfl_xor_sync(0xffffffffu, d, o);
            float s = fmaf(-2.0f, d, g_c2[idx]);
            if (s < bS || (s == bS && idx < bI)) { bS = s; bI = idx; }
        }
        // non-candidates have exact score >= v - delta; need strict win
        if (!(bS < v - delta)) {
            // rare coalesced full scan: warp cooperates per code, 8 codes in flight
            for (int c0 = 0; c0 < 1024; c0 += 8) {
                float d[8];
                #pragma unroll
                for (int cc = 0; cc < 8; cc++) {
                    const float4* c4 = (const float4*)(cb + (size_t)(c0 + cc) * 256) + lane * 2;
                    float4 xa = c4[0], xb = c4[1];
                    d[cc] = za.x*xa.x + za.y*xa.y + za.z*xa.z + za.w*xa.w
                          + zb.x*xb.x + zb.y*xb.y + zb.z*xb.z + zb.w*xb.w;
                }
                #pragma unroll
                for (int cc = 0; cc < 8; cc++) {
                    #pragma unroll
                    for (int o = 16; o; o >>= 1) d[cc] += __shfl_xor_sync(0xffffffffu, d[cc], o);
                }
                #pragma unroll
                for (int cc = 0; cc < 8; cc++) {
                    float s = fmaf(-2.0f, d[cc], g_c2[c0 + cc]);
                    int  cix = c0 + cc;
                    if (s < bS || (s == bS && cix < bI)) { bS = s; bI = cix; }
                }
            }
        }
    }

    const int idx = bI;
    const float m = mask[token];
    const float4* q4 = (const float4*)(cb + (size_t)idx * 256) + lane * 2;
    float4 qa = q4[0], qb = q4[1];

    float ss = 0.0f;
    {
        float dx = za.x - qa.x, dy = za.y - qa.y, dz = za.z - qa.z, dw = za.w - qa.w;
        ss += dx*dx + dy*dy + dz*dz + dw*dw;
        dx = zb.x - qb.x; dy = zb.y - qb.y; dz = zb.z - qb.z; dw = zb.w - qb.w;
        ss += dx*dx + dy*dy + dz*dz + dw*dw;
    }
    float4* o4 = (float4*)(outQ + (size_t)token * 256) + lane * 2;
    float4 oa, ob;
    oa.x = (za.x + (qa.x - za.x)) * m; oa.y = (za.y + (qa.y - za.y)) * m;
    oa.z = (za.z + (qa.z - za.z)) * m; oa.w = (za.w + (qa.w - za.w)) * m;
    ob.x = (zb.x + (qb.x - zb.x)) * m; ob.y = (zb.y + (qb.y - zb.y)) * m;
    ob.z = (zb.z + (qb.z - zb.z)) * m; ob.w = (zb.w + (qb.w - zb.w)) * m;
    o4[0] = oa; o4[1] = ob;

    #pragma unroll
    for (int o = 16; o; o >>= 1) ss += __shfl_down_sync(0xffffffffu, ss, o);
    if (lane == 0) {
        sSum[warp] = ss * m;
        sM[warp]   = m;
        outIdx[token] = (m > 0.0f) ? (float)idx : 0.0f;
    }
    __syncthreads();
    if (threadIdx.x == 0) {
        float a = 0.0f, b = 0.0f;
        #pragma unroll
        for (int w = 0; w < 8; w++) { a += sSum[w]; b += sM[w]; }
        atomicAdd(&g_accum[0], a);
        atomicAdd(&g_accum[1], b);
    }
}

__global__ void k_finalize(float* outLoss) {
    outLoss[0] = 0.25f * (g_accum[0] / (g_accum[1] * 256.0f));
}

// ─────────────── launcher ───────────────
extern "C" void kernel_launch(void* const* d_in, const int* in_sizes, int n_in,
                              void* d_out, int out_size) {
    const float* z    = (const float*)d_in[0];   // (B,S,D)
    const float* mask = (const float*)d_in[1];   // (B,S)
    const float* cb   = (const float*)d_in[2];   // (K,D)

    const int BSD = in_sizes[0];                 // 8388608
    const int N   = in_sizes[1];                 // 32768

    float* out     = (float*)d_out;
    float* outQ    = out;
    float* outLoss = out + BSD;
    float* outIdx  = out + BSD + 1;

    cudaFuncSetAttribute(k_mma, cudaFuncAttributeMaxDynamicSharedMemorySize, DYN_SMEM);

    k_init<<<1, 1>>>();
    k_c2<<<128, 256>>>((const float4*)cb);
    k_mma<<<N / 128, 256, DYN_SMEM>>>(z, cb);
    k_select<<<N / 8, 256>>>(z, mask, cb, outQ, outIdx);
    k_finalize<<<1, 1>>>(outLoss);
}